// round 7
// baseline (speedup 1.0000x reference)
#include <cuda_runtime.h>
#include <math.h>

#define N_NODES 100000
#define N_EDGES 1600000
#define IN_F 128
#define OUT_F 32
#define NEG_SLOPE 0.2f

#define ROWS_PB 128
#define K1_BLOCKS ((N_NODES + ROWS_PB - 1) / ROWS_PB)   // 782

#define NB_E 128                 // blocks in fused edge kernel (all co-resident)
#define SCAN_BLKS 98             // 98 * 1024 = 100352 >= N_NODES

// Scratch (device globals: no allocation allowed; zero-initialized at load)
__device__ float g_z[(size_t)N_NODES * OUT_F];
__device__ float g_el[N_NODES];
__device__ float g_er[N_NODES];
__device__ int   g_cnt[N_NODES];     // per-node edge count (zero on entry, reset by k_aggregate)
__device__ int   g_off[N_NODES];     // CSR offsets; after scatter = end offsets
__device__ int   g_bsum[SCAN_BLKS];  // scan block sums
__device__ int   g_bar;              // monotone grid-barrier ticket counter
__device__ int2  g_srcex[N_EDGES];   // (src, ex-bits) sorted by dst

// ---------------------------------------------------------------------------
// packed f32x2 helpers (sm_100+; bit-identical per-lane rounding to fmaf)
// ---------------------------------------------------------------------------
__device__ __forceinline__ unsigned long long pack2(float x) {
    unsigned long long r;
    unsigned u = __float_as_uint(x);
    asm("mov.b64 %0, {%1, %1};" : "=l"(r) : "r"(u));
    return r;
}
__device__ __forceinline__ void fma2(unsigned long long& d,
                                     unsigned long long a, unsigned long long b) {
    asm("fma.rn.f32x2 %0, %1, %2, %0;" : "+l"(d) : "l"(a), "l"(b));
}
__device__ __forceinline__ float2 unpack2(unsigned long long v) {
    unsigned lo, hi;
    asm("mov.b64 {%0, %1}, %2;" : "=r"(lo), "=r"(hi) : "l"(v));
    return make_float2(__uint_as_float(lo), __uint_as_float(hi));
}

// ---------------------------------------------------------------------------
// K1: z = h @ W^T, el/er row dots. Tile 4 rows x 4 cols (as 2 f32x2 pairs).
// h direct from global (broadcast LDG.128 per 8-lane group); W in shared.
// Inner product uses FFMA2 -> half the FMA-pipe ops.
// ---------------------------------------------------------------------------
__global__ __launch_bounds__(256, 3) void k_gemm(
    const float* __restrict__ h, const float* __restrict__ W,
    const float* __restrict__ a)
{
    __shared__ float Wt[IN_F][OUT_F];       // 16 KB, Wt[k][j] = W[j][k]

    const int tid      = threadIdx.x;
    const int col0     = (tid & 7) * 4;     // 4 cols per thread
    const int row_grp  = tid >> 3;          // 32 groups x 4 rows = 128 rows
    const int row_base = blockIdx.x * ROWS_PB + row_grp * 4;

    for (int i = tid; i < IN_F * OUT_F; i += 256) {
        int j = i >> 7;
        int k = i & 127;
        Wt[k][j] = W[i];
    }
    __syncthreads();

    int rows[4];
    #pragma unroll
    for (int i = 0; i < 4; i++) {
        int r = row_base + i;
        rows[i] = (r < N_NODES) ? r : (N_NODES - 1);
    }

    const float4* h4 = (const float4*)h;    // row stride = 32 float4

    unsigned long long acc01[4], acc23[4];
    #pragma unroll
    for (int i = 0; i < 4; i++) { acc01[i] = 0ull; acc23[i] = 0ull; }

    #pragma unroll 4
    for (int k4 = 0; k4 < IN_F / 4; k4++) {
        ulonglong2 w0 = *(const ulonglong2*)&Wt[k4 * 4 + 0][col0];
        ulonglong2 w1 = *(const ulonglong2*)&Wt[k4 * 4 + 1][col0];
        ulonglong2 w2 = *(const ulonglong2*)&Wt[k4 * 4 + 2][col0];
        ulonglong2 w3 = *(const ulonglong2*)&Wt[k4 * 4 + 3][col0];

        #pragma unroll
        for (int i = 0; i < 4; i++) {
            float4 hv = h4[(size_t)rows[i] * (IN_F / 4) + k4];
            unsigned long long hx = pack2(hv.x);
            unsigned long long hy = pack2(hv.y);
            unsigned long long hz = pack2(hv.z);
            unsigned long long hw = pack2(hv.w);
            fma2(acc01[i], hx, w0.x); fma2(acc23[i], hx, w0.y);
            fma2(acc01[i], hy, w1.x); fma2(acc23[i], hy, w1.y);
            fma2(acc01[i], hz, w2.x); fma2(acc23[i], hz, w2.y);
            fma2(acc01[i], hw, w3.x); fma2(acc23[i], hw, w3.y);
        }
    }

    const float4 al4 = *(const float4*)&a[col0];
    const float4 ar4 = *(const float4*)&a[OUT_F + col0];

    #pragma unroll
    for (int i = 0; i < 4; i++) {
        int r = row_base + i;
        bool ok = (r < N_NODES);
        float2 p01 = unpack2(acc01[i]);
        float2 p23 = unpack2(acc23[i]);
        float4 av = make_float4(p01.x, p01.y, p23.x, p23.y);

        if (ok)
            *(float4*)&g_z[(size_t)r * OUT_F + col0] = av;

        float pel = av.x * al4.x + av.y * al4.y + av.z * al4.z + av.w * al4.w;
        float per = av.x * ar4.x + av.y * ar4.y + av.z * ar4.z + av.w * ar4.w;
        #pragma unroll
        for (int o = 4; o > 0; o >>= 1) {
            pel += __shfl_xor_sync(0xffffffffu, pel, o);
            per += __shfl_xor_sync(0xffffffffu, per, o);
        }
        if (ok && (tid & 7) == 0) {
            g_el[r] = pel;
            g_er[r] = per;
        }
    }
}

// ---------------------------------------------------------------------------
// Grid barrier via monotone ticket counter (all NB_E blocks co-resident:
// 128 blocks x 1024 thr, <=64 regs, ~4.5KB smem -> 1 block/SM floor, 128<148).
// Works across graph replays without reset (counter only grows).
// ---------------------------------------------------------------------------
__device__ __forceinline__ void grid_barrier()
{
    __syncthreads();
    if (threadIdx.x == 0) {
        __threadfence();
        int ticket = atomicAdd(&g_bar, 1);
        int target = (ticket / NB_E + 1) * NB_E;
        while (*((volatile int*)&g_bar) < target) { }
        __threadfence();
    }
    __syncthreads();
}

// ---------------------------------------------------------------------------
// K2 (fused): histogram -> exclusive scan of counts -> scatter edges into
// dst-sorted CSR order with ex = exp(leaky_relu(el[src]+er[dst])).
// (segment-max shift dropped: cancels algebraically in alpha; |e| small)
// After phase 2, g_off[n] = end offset of node n's edge run.
// ---------------------------------------------------------------------------
__global__ __launch_bounds__(1024) void k_edges(
    const int* __restrict__ src, const int* __restrict__ dst)
{
    __shared__ int s[1024];
    __shared__ int s2[128];

    const int tid = threadIdx.x;
    const int bid = blockIdx.x;

    // --- phase 0: histogram of dst (g_cnt is zero on entry by invariant) ---
    for (int e = bid * 1024 + tid; e < N_EDGES; e += NB_E * 1024)
        atomicAdd(&g_cnt[dst[e]], 1);

    grid_barrier();

    // --- phase 1a: per-block inclusive scan of counts (blocks 0..97) ---
    const bool valid = (bid < SCAN_BLKS);
    const int  i     = bid * 1024 + tid;
    int c = 0, excl = 0;
    if (valid) {
        c = (i < N_NODES) ? g_cnt[i] : 0;
        s[tid] = c;
        __syncthreads();
        #pragma unroll
        for (int o = 1; o < 1024; o <<= 1) {
            int v = (tid >= o) ? s[tid - o] : 0;
            __syncthreads();
            s[tid] += v;
            __syncthreads();
        }
        excl = s[tid] - c;
        if (tid == 1023) g_bsum[bid] = s[tid];
    }

    grid_barrier();

    // --- phase 1b: add prefix of block sums, write final offsets ---
    if (valid) {
        if (tid < 128) s2[tid] = (tid < bid) ? g_bsum[tid] : 0;
        __syncthreads();
        #pragma unroll
        for (int o = 64; o > 0; o >>= 1) {
            if (tid < o) s2[tid] += s2[tid + o];
            __syncthreads();
        }
        if (i < N_NODES) g_off[i] = excl + s2[0];
    }

    grid_barrier();

    // --- phase 2: scatter (src, ex) into CSR slots ---
    for (int e = bid * 1024 + tid; e < N_EDGES; e += NB_E * 1024) {
        int sn = src[e];
        int d  = dst[e];
        float v = g_el[sn] + g_er[d];
        v = (v > 0.0f) ? v : NEG_SLOPE * v;
        float ex = __expf(v);
        int pos = atomicAdd(&g_off[d], 1);
        g_srcex[pos] = make_int2(sn, __float_as_int(ex));
    }
}

// ---------------------------------------------------------------------------
// K3: one warp per node: out[n] = (sum_e ex_e * z[src_e]) / (sum_e ex_e).
// 8 lanes per edge (float4 each), 4 edges in parallel per warp.
// Writes every out element -> no zero-init, no float atomics anywhere.
// Resets g_cnt for the next replay (maintains the zero-on-entry invariant).
// ---------------------------------------------------------------------------
__global__ __launch_bounds__(256) void k_aggregate(float* __restrict__ out)
{
    int node = blockIdx.x * 8 + (threadIdx.x >> 5);
    if (node >= N_NODES) return;
    int lane = threadIdx.x & 31;
    int seg  = lane & 7;      // float4 index within row
    int grp  = lane >> 3;     // 0..3: which edge of a 4-edge batch

    int end   = g_off[node];  // end offset after scatter
    int cnt   = g_cnt[node];
    int start = end - cnt;

    if (lane == 0) g_cnt[node] = 0;   // invariant for next replay

    float4 acc = make_float4(0.f, 0.f, 0.f, 0.f);
    float exsum = 0.0f;

    for (int j = grp; j < cnt; j += 4) {
        int2 se = g_srcex[start + j];            // broadcast within group
        int sn = se.x;
        float ex = __int_as_float(se.y);
        float4 zv = ((const float4*)(g_z + (size_t)sn * OUT_F))[seg];
        acc.x = fmaf(ex, zv.x, acc.x);
        acc.y = fmaf(ex, zv.y, acc.y);
        acc.z = fmaf(ex, zv.z, acc.z);
        acc.w = fmaf(ex, zv.w, acc.w);
        exsum += ex;
    }

    #pragma unroll
    for (int o = 8; o <= 16; o <<= 1) {
        acc.x += __shfl_xor_sync(0xffffffffu, acc.x, o);
        acc.y += __shfl_xor_sync(0xffffffffu, acc.y, o);
        acc.z += __shfl_xor_sync(0xffffffffu, acc.z, o);
        acc.w += __shfl_xor_sync(0xffffffffu, acc.w, o);
        exsum += __shfl_xor_sync(0xffffffffu, exsum, o);
    }

    float inv = 1.0f / fmaxf(exsum, 1e-16f);
    if (grp == 0) {
        float4 r = make_float4(acc.x * inv, acc.y * inv, acc.z * inv, acc.w * inv);
        ((float4*)(out + (size_t)node * OUT_F))[seg] = r;
    }
}

// ---------------------------------------------------------------------------
extern "C" void kernel_launch(void* const* d_in, const int* in_sizes, int n_in,
                              void* d_out, int out_size)
{
    const float* h   = (const float*)d_in[0];
    const float* W   = (const float*)d_in[1];
    const float* a   = (const float*)d_in[2];
    const int*   src = (const int*)d_in[3];
    const int*   dst = (const int*)d_in[4];
    float* out = (float*)d_out;

    (void)in_sizes; (void)n_in; (void)out_size;

    k_gemm<<<K1_BLOCKS, 256>>>(h, W, a);          // 782 blocks
    k_edges<<<NB_E, 1024>>>(src, dst);            // 128 blocks, fused pipeline
    k_aggregate<<<(N_NODES + 7) / 8, 256>>>(out); // 12500 blocks
}

// round 8
// speedup vs baseline: 1.5648x; 1.5648x over previous
#include <cuda_runtime.h>
#include <math.h>

#define N_NODES 100000
#define N_EDGES 1600000
#define IN_F 128
#define OUT_F 32
#define NEG_SLOPE 0.2f

#define ROWS_PB 64
#define K1_THREADS 128
#define K1_BLOCKS ((N_NODES + ROWS_PB - 1) / ROWS_PB)   // 1563

#define SCAN_CHUNK 1024
#define SCAN_BLOCKS ((N_NODES + SCAN_CHUNK - 1) / SCAN_CHUNK)  // 98

// Scratch (device globals: no allocation allowed)
__device__ float g_z[(size_t)N_NODES * OUT_F];
__device__ float g_el[N_NODES];
__device__ float g_er[N_NODES];
__device__ int   g_cnt[N_NODES];      // per-node edge count
__device__ int   g_off[N_NODES];      // exclusive prefix (CSR row starts)
__device__ int   g_cur[N_NODES];      // scatter cursors
__device__ int   g_bsum[SCAN_BLOCKS]; // scan block sums
__device__ int2  g_srcex[N_EDGES];    // (src, ex-bits) sorted by dst

// ---------------------------------------------------------------------------
// packed f32x2 helpers (sm_100+; bit-identical per-lane rounding to fmaf)
// ---------------------------------------------------------------------------
__device__ __forceinline__ unsigned long long pack2(float x) {
    unsigned long long r;
    unsigned u = __float_as_uint(x);
    asm("mov.b64 %0, {%1, %1};" : "=l"(r) : "r"(u));
    return r;
}
__device__ __forceinline__ void fma2(unsigned long long& d,
                                     unsigned long long a, unsigned long long b) {
    asm("fma.rn.f32x2 %0, %1, %2, %0;" : "+l"(d) : "l"(a), "l"(b));
}
__device__ __forceinline__ float2 unpack2(unsigned long long v) {
    unsigned lo, hi;
    asm("mov.b64 {%0, %1}, %2;" : "=r"(lo), "=r"(hi) : "l"(v));
    return make_float2(__uint_as_float(lo), __uint_as_float(hi));
}

// bank-swizzle rotation for the h tile: rows {i, i+4, i+8, i+12} land on
// distinct 16B bank-quads ( (r + r>>3) mod 8 distinct for r-diff 4,8,12 )
__device__ __forceinline__ int rot(int r) { return (r + (r >> 3)) & 31; }

// ---------------------------------------------------------------------------
// K1: z = h @ W^T, el/er row dots. 128 threads, 64 rows/block.
// Phase 1: stage h tile to smem with 16 independent LDG.128 per thread
//          (MLP 16 -> multi-TB/s stream), swizzled columns.
// Phase 2: tile 4 rows x 4 cols per thread, FFMA2 inner product from smem
//          (8 LDS.128 per 32 FFMA2 -> FMA-pipe bound).
// Also zeros g_cnt / g_cur (grid has 200k threads).
// ---------------------------------------------------------------------------
__global__ __launch_bounds__(K1_THREADS) void k_gemm(
    const float* __restrict__ h, const float* __restrict__ W,
    const float* __restrict__ a)
{
    __shared__ float4 hs4[ROWS_PB * (IN_F / 4)];   // 32 KB, swizzled
    __shared__ float  Wt[IN_F][OUT_F];             // 16 KB, Wt[k][j] = W[j][k]

    const int tid  = threadIdx.x;
    const int row0 = blockIdx.x * ROWS_PB;

    // zero cnt + cur (1563*128 = 200k threads covers 100k nodes)
    {
        int i = blockIdx.x * K1_THREADS + tid;
        if (i < N_NODES) { g_cnt[i] = 0; g_cur[i] = 0; }
    }

    // stage W transposed
    for (int i = tid; i < IN_F * OUT_F; i += K1_THREADS) {
        int j = i >> 7;
        int k = i & 127;
        Wt[k][j] = W[i];
    }

    // stage h tile: 2048 float4s / 128 threads = 16 independent loads
    {
        const float4* h4 = (const float4*)h;
        #pragma unroll
        for (int it = 0; it < 16; it++) {
            int idx = it * K1_THREADS + tid;      // [64 rows][32 f4]
            int r = idx >> 5;
            int c = idx & 31;
            int gr = row0 + r;
            if (gr >= N_NODES) gr = N_NODES - 1;  // clamp (stores predicated)
            hs4[r * 32 + ((c + rot(r)) & 31)] = h4[(size_t)gr * 32 + c];
        }
    }
    __syncthreads();

    const int col0  = (tid & 7) * 4;              // 4 cols per thread
    const int rbase = (tid >> 3) * 4;             // 16 groups x 4 rows

    unsigned long long acc01[4], acc23[4];
    #pragma unroll
    for (int i = 0; i < 4; i++) { acc01[i] = 0ull; acc23[i] = 0ull; }

    #pragma unroll 4
    for (int k4 = 0; k4 < IN_F / 4; k4++) {
        ulonglong2 w0 = *(const ulonglong2*)&Wt[k4 * 4 + 0][col0];
        ulonglong2 w1 = *(const ulonglong2*)&Wt[k4 * 4 + 1][col0];
        ulonglong2 w2 = *(const ulonglong2*)&Wt[k4 * 4 + 2][col0];
        ulonglong2 w3 = *(const ulonglong2*)&Wt[k4 * 4 + 3][col0];

        #pragma unroll
        for (int i = 0; i < 4; i++) {
            int r = rbase + i;
            float4 hv = hs4[r * 32 + ((k4 + rot(r)) & 31)];
            unsigned long long hx = pack2(hv.x);
            unsigned long long hy = pack2(hv.y);
            unsigned long long hz = pack2(hv.z);
            unsigned long long hw = pack2(hv.w);
            fma2(acc01[i], hx, w0.x); fma2(acc23[i], hx, w0.y);
            fma2(acc01[i], hy, w1.x); fma2(acc23[i], hy, w1.y);
            fma2(acc01[i], hz, w2.x); fma2(acc23[i], hz, w2.y);
            fma2(acc01[i], hw, w3.x); fma2(acc23[i], hw, w3.y);
        }
    }

    const float4 al4 = *(const float4*)&a[col0];
    const float4 ar4 = *(const float4*)&a[OUT_F + col0];

    #pragma unroll
    for (int i = 0; i < 4; i++) {
        int r = row0 + rbase + i;
        bool ok = (r < N_NODES);
        float2 p01 = unpack2(acc01[i]);
        float2 p23 = unpack2(acc23[i]);
        float4 av = make_float4(p01.x, p01.y, p23.x, p23.y);

        if (ok)
            *(float4*)&g_z[(size_t)r * OUT_F + col0] = av;

        float pel = av.x * al4.x + av.y * al4.y + av.z * al4.z + av.w * al4.w;
        float per = av.x * ar4.x + av.y * ar4.y + av.z * ar4.z + av.w * ar4.w;
        #pragma unroll
        for (int o = 4; o > 0; o >>= 1) {
            pel += __shfl_xor_sync(0xffffffffu, pel, o);
            per += __shfl_xor_sync(0xffffffffu, per, o);
        }
        if (ok && (tid & 7) == 0) {
            g_el[r] = pel;
            g_er[r] = per;
        }
    }
}

// ---------------------------------------------------------------------------
// A: histogram of dst
// ---------------------------------------------------------------------------
__global__ __launch_bounds__(256) void k_hist(const int* __restrict__ dst)
{
    int e = blockIdx.x * 256 + threadIdx.x;
    if (e < N_EDGES) atomicAdd(&g_cnt[dst[e]], 1);
}

// ---------------------------------------------------------------------------
// B1: per-chunk exclusive scan of g_cnt -> g_off (local), block sum -> g_bsum
// ---------------------------------------------------------------------------
__global__ __launch_bounds__(SCAN_CHUNK) void k_scan_local()
{
    __shared__ int s[SCAN_CHUNK];
    int t = threadIdx.x;
    int i = blockIdx.x * SCAN_CHUNK + t;
    int c = (i < N_NODES) ? g_cnt[i] : 0;
    s[t] = c;
    __syncthreads();
    #pragma unroll
    for (int off = 1; off < SCAN_CHUNK; off <<= 1) {
        int v = (t >= off) ? s[t - off] : 0;
        __syncthreads();
        s[t] += v;
        __syncthreads();
    }
    if (i < N_NODES) g_off[i] = s[t] - c;        // exclusive (local)
    if (t == SCAN_CHUNK - 1) g_bsum[blockIdx.x] = s[t];
}

// ---------------------------------------------------------------------------
// B2: each block tree-reduces its own prefix of block sums and adds it.
// (replaces the serial single-block bsum scan + separate add kernel)
// ---------------------------------------------------------------------------
__global__ __launch_bounds__(SCAN_CHUNK) void k_scan_add()
{
    __shared__ int s2[128];
    int t = threadIdx.x;
    if (t < 128) s2[t] = (t < blockIdx.x) ? g_bsum[t] : 0;   // blockIdx < 98
    __syncthreads();
    #pragma unroll
    for (int o = 64; o > 0; o >>= 1) {
        if (t < o) s2[t] += s2[t + o];
        __syncthreads();
    }
    int i = blockIdx.x * SCAN_CHUNK + t;
    if (i < N_NODES) g_off[i] += s2[0];
}

// ---------------------------------------------------------------------------
// C: per-edge ex = exp(leaky_relu(el[src]+er[dst])); scatter (src, ex)
//    into dst-sorted CSR order. (max-shift dropped: cancels in alpha.)
// ---------------------------------------------------------------------------
__global__ __launch_bounds__(256) void k_scatter(
    const int* __restrict__ src, const int* __restrict__ dst)
{
    int e = blockIdx.x * 256 + threadIdx.x;
    if (e >= N_EDGES) return;
    int sn = src[e];
    int d  = dst[e];
    float v = g_el[sn] + g_er[d];
    v = (v > 0.0f) ? v : NEG_SLOPE * v;
    float ex = __expf(v);
    int pos = g_off[d] + atomicAdd(&g_cur[d], 1);
    g_srcex[pos] = make_int2(sn, __float_as_int(ex));
}

// ---------------------------------------------------------------------------
// D: one warp per node: out[n] = (sum_e ex_e * z[src_e]) / (sum_e ex_e)
// 8 lanes per edge (float4 each), 4 edges in parallel per warp.
// Writes every out element -> no zero-init, no float atomics anywhere.
// ---------------------------------------------------------------------------
__global__ __launch_bounds__(256) void k_aggregate(float* __restrict__ out)
{
    int node = blockIdx.x * 8 + (threadIdx.x >> 5);
    if (node >= N_NODES) return;
    int lane = threadIdx.x & 31;
    int seg  = lane & 7;      // float4 index within row
    int grp  = lane >> 3;     // 0..3: which edge of a 4-edge batch

    int start = g_off[node];
    int cnt   = g_cnt[node];

    float4 acc = make_float4(0.f, 0.f, 0.f, 0.f);
    float exsum = 0.0f;

    for (int j = grp; j < cnt; j += 4) {
        int2 se = g_srcex[start + j];            // broadcast within group
        int sn = se.x;
        float ex = __int_as_float(se.y);
        float4 zv = ((const float4*)(g_z + (size_t)sn * OUT_F))[seg];
        acc.x = fmaf(ex, zv.x, acc.x);
        acc.y = fmaf(ex, zv.y, acc.y);
        acc.z = fmaf(ex, zv.z, acc.z);
        acc.w = fmaf(ex, zv.w, acc.w);
        exsum += ex;
    }

    #pragma unroll
    for (int o = 8; o <= 16; o <<= 1) {
        acc.x += __shfl_xor_sync(0xffffffffu, acc.x, o);
        acc.y += __shfl_xor_sync(0xffffffffu, acc.y, o);
        acc.z += __shfl_xor_sync(0xffffffffu, acc.z, o);
        acc.w += __shfl_xor_sync(0xffffffffu, acc.w, o);
        exsum += __shfl_xor_sync(0xffffffffu, exsum, o);
    }

    float inv = 1.0f / fmaxf(exsum, 1e-16f);
    if (grp == 0) {
        float4 r = make_float4(acc.x * inv, acc.y * inv, acc.z * inv, acc.w * inv);
        ((float4*)(out + (size_t)node * OUT_F))[seg] = r;
    }
}

// ---------------------------------------------------------------------------
extern "C" void kernel_launch(void* const* d_in, const int* in_sizes, int n_in,
                              void* d_out, int out_size)
{
    const float* h   = (const float*)d_in[0];
    const float* W   = (const float*)d_in[1];
    const float* a   = (const float*)d_in[2];
    const int*   src = (const int*)d_in[3];
    const int*   dst = (const int*)d_in[4];
    float* out = (float*)d_out;

    (void)in_sizes; (void)n_in; (void)out_size;

    k_gemm<<<K1_BLOCKS, K1_THREADS>>>(h, W, a);              // 1563 blocks
    k_hist<<<(N_EDGES + 255) / 256, 256>>>(dst);             // 6250
    k_scan_local<<<SCAN_BLOCKS, SCAN_CHUNK>>>();             // 98
    k_scan_add<<<SCAN_BLOCKS, SCAN_CHUNK>>>();               // 98
    k_scatter<<<(N_EDGES + 255) / 256, 256>>>(src, dst);     // 6250
    k_aggregate<<<(N_NODES + 7) / 8, 256>>>(out);            // 12500
}